// round 15
// baseline (speedup 1.0000x reference)
#include <cuda_runtime.h>
#include <cuda_bf16.h>
#include <math.h>
#include <stdint.h>

#define BDIM 8192
#define FDIM 1024
#define EDIM 30
#define HDIM 256
#define CDIM 100
#define GDIM 4096
#define EPSV 1e-8f

#define TBR  32
#define NTHR 256
#define MAXT 288
#define NC1  32      /* 1024/32 k-chunks GEMM1 */
#define NC2  8       /* 256/32  k-chunks GEMM2 */

/* ---- dynamic smem layout (bytes) ---- */
#define LDW    80        /* row stride A1/B1/B2: 40 bf16 */
#define A1HL   2560      /* 32 rows x 80B */
#define A1BUF  5120
#define A1_OFF 0
#define B1_OFF 10240
#define B1HL   20480
#define B1BUF  40960     /* x2 buffers -> region 81920 */
#define PARB1  92160
#define PARGM  93184
#define PARBT  94208
#define PARB2  95232
#define PSUM_OFF 96256   /* 32 rows x 8 groups */
#define PSQ_OFF  97280
#define MURS_OFF 98304   /* 32 float2 */
#define DYNB   99328
/* phase-2 regions live inside the B1 region */
#define A2_OFF 10240
#define A2HL   16896     /* 32 x 528 */
#define LDA2   528
#define B2_OFF 45056
#define B2HL   10240
#define B2BUF  20480

__device__ int   g_assign[BDIM];
__device__ int   g_counts[EDIM];
__device__ int   g_cursor[EDIM];
__device__ float g_escale[EDIM];
__device__ int   g_sorted[BDIM];

__device__ __forceinline__ float warp_sum(float v){
  #pragma unroll
  for (int o=16;o>0;o>>=1) v += __shfl_xor_sync(0xffffffffu, v, o);
  return v;
}

__device__ __forceinline__ uint32_t smem_u32(const void* p){
  uint32_t a;
  asm("{ .reg .u64 t; cvta.to.shared.u64 t, %1; cvt.u32.u64 %0, t; }" : "=r"(a) : "l"(p));
  return a;
}

__device__ __forceinline__ void split2(float v0, float v1, uint32_t& hi, uint32_t& lo){
  __nv_bfloat16 h0 = __float2bfloat16(v0), h1 = __float2bfloat16(v1);
  float r0 = v0 - __bfloat162float(h0), r1 = v1 - __bfloat162float(h1);
  __nv_bfloat162 hp; hp.x = h0; hp.y = h1;
  __nv_bfloat162 lp = __floats2bfloat162_rn(r0, r1);
  hi = *(uint32_t*)&hp; lo = *(uint32_t*)&lp;
}

__device__ __forceinline__ void ldsm4(uint32_t* r, uint32_t a){
  asm volatile("ldmatrix.sync.aligned.m8n8.x4.shared.b16 {%0,%1,%2,%3}, [%4];"
    : "=r"(r[0]),"=r"(r[1]),"=r"(r[2]),"=r"(r[3]) : "r"(a));
}
__device__ __forceinline__ void mma_bf16(float* d, const uint32_t* a, uint32_t b0, uint32_t b1){
  asm volatile("mma.sync.aligned.m16n8k16.row.col.f32.bf16.bf16.f32 "
    "{%0,%1,%2,%3}, {%4,%5,%6,%7}, {%8,%9}, {%0,%1,%2,%3};"
    : "+f"(d[0]),"+f"(d[1]),"+f"(d[2]),"+f"(d[3])
    : "r"(a[0]),"r"(a[1]),"r"(a[2]),"r"(a[3]), "r"(b0),"r"(b1));
}
__device__ __forceinline__ float gelu(float v){
  return 0.5f*v*(1.0f + erff(v*0.70710678118654752f));
}

// ---------------------------------------------------------------------------
__global__ void prep_kernel(const float* __restrict__ protos,
                            const float* __restrict__ gnew,
                            const float* __restrict__ gmem,
                            const int*   __restrict__ class_counts){
  int e = blockIdx.x;
  int t = threadIdx.x, lane = t & 31, w = t >> 5;
  __shared__ float red[4][4];
  if (t == 0){ g_counts[e] = 0; g_cursor[e] = 0; }
  float d = 0.f, m2 = 0.f, n2 = 0.f;
  for (int i = t; i < GDIM; i += 128){
    float a = gmem[(size_t)e*GDIM + i];
    float b = gnew[i];
    d += a*b; m2 += a*a; n2 += b*b;
  }
  float p2 = 0.f;
  for (int f = t; f < FDIM; f += 128){
    float p = protos[(size_t)e*FDIM + f];
    p2 += p*p;
  }
  d = warp_sum(d); m2 = warp_sum(m2); n2 = warp_sum(n2); p2 = warp_sum(p2);
  if (lane == 0){ red[w][0]=d; red[w][1]=m2; red[w][2]=n2; red[w][3]=p2; }
  __syncthreads();
  if (t == 0){
    float D=0.f,M=0.f,N=0.f,P=0.f;
    #pragma unroll
    for (int i=0;i<4;i++){ D+=red[i][0]; M+=red[i][1]; N+=red[i][2]; P+=red[i][3]; }
    float align = 0.5f*(1.0f + D/((sqrtf(M)+EPSV)*(sqrtf(N)+EPSV)));
    float over  = fmaxf((float)class_counts[e]/5.0f - 1.0f, 0.0f);
    float cap   = expf(-1.5f*over);
    g_escale[e] = align*cap/(sqrtf(P)+EPSV);
  }
}

__global__ __launch_bounds__(256, 2) void route_kernel(
    const float* __restrict__ x, const float* __restrict__ protos){
  __shared__ float xt[64][33];
  __shared__ float pr[30][64];
  __shared__ float sc[32][32];
  const int t = threadIdx.x;
  const int sample = t & 31;
  const int egr    = t >> 5;
  const int s0 = blockIdx.x * 32;

  float acc[4] = {0.f,0.f,0.f,0.f};
  for (int kt = 0; kt < 16; ++kt){
    __syncthreads();
    {
      int kk = t & 63, rr = t >> 6;
      #pragma unroll
      for (int i=0;i<8;i++){
        int r = rr + 4*i;
        xt[kk][r] = x[(size_t)(s0 + r)*FDIM + kt*64 + kk];
      }
    }
    #pragma unroll
    for (int i=0;i<8;i++){
      int idx = t + 256*i;
      if (idx < 1920)
        pr[idx >> 6][idx & 63] = protos[(size_t)(idx >> 6)*FDIM + kt*64 + (idx & 63)];
    }
    __syncthreads();
    #pragma unroll
    for (int k4 = 0; k4 < 16; ++k4){
      float x0 = xt[4*k4+0][sample], x1 = xt[4*k4+1][sample];
      float x2 = xt[4*k4+2][sample], x3 = xt[4*k4+3][sample];
      #pragma unroll
      for (int e4 = 0; e4 < 4; ++e4){
        int e = egr*4 + e4;
        if (e < EDIM){
          float4 p = *(const float4*)&pr[e][4*k4];
          acc[e4] += x0*p.x + x1*p.y + x2*p.z + x3*p.w;
        }
      }
    }
  }
  #pragma unroll
  for (int e4 = 0; e4 < 4; ++e4){
    int e = egr*4 + e4;
    if (e < 32) sc[sample][e & 31] = (e < EDIM) ? acc[e4] : 0.f;
  }
  __syncthreads();
  if (t < 32){
    float best = -3.4e38f; int bi = 0;
    #pragma unroll 1
    for (int e = 0; e < EDIM; ++e){
      float s = sc[t][e] * g_escale[e];
      if (s > best){ best = s; bi = e; }
    }
    g_assign[s0 + t] = bi;
    atomicAdd(&g_counts[bi], 1);
  }
}

__global__ void scatter_kernel(){
  __shared__ int base[EDIM];
  if (threadIdx.x == 0){
    int off = 0;
    #pragma unroll
    for (int e=0;e<EDIM;e++){ base[e] = off; off += g_counts[e]; }
  }
  __syncthreads();
  int b = blockIdx.x*blockDim.x + threadIdx.x;
  if (b < BDIM){
    int e = g_assign[b];
    int pos = base[e] + atomicAdd(&g_cursor[e], 1);
    g_sorted[pos] = b;
  }
}

// ---------------------------------------------------------------------------
// MLP: 32-row tiles, 256 threads, 2 CTAs/SM. Per-warp inner loop identical to
// the proven 32x32-tile bf16 split mma.sync path.
// ---------------------------------------------------------------------------
__global__ __launch_bounds__(NTHR, 2)
void mlp_kernel(const float* __restrict__ x,  const float* __restrict__ W1,
                const float* __restrict__ b1, const float* __restrict__ gamma,
                const float* __restrict__ beta, const float* __restrict__ W2,
                const float* __restrict__ b2, float* __restrict__ out)
{
  extern __shared__ __align__(128) char smc[];
  __shared__ int ridx[TBR];
  __shared__ int s_meta[3];

  const int t    = threadIdx.x;
  const int lane = t & 31;
  const int w    = t >> 5;        // 0..7

  if (t == 0){
    int off = 0, tcum = 0, e = -1, row0 = 0, nv = 0;
    #pragma unroll 1
    for (int ee=0; ee<EDIM; ee++){
      int n  = g_counts[ee];
      int nt = (n + TBR - 1) / TBR;
      if (e < 0 && (int)blockIdx.x < tcum + nt){
        int li = (int)blockIdx.x - tcum;
        e = ee; row0 = off + li*TBR;
        nv = n - li*TBR; if (nv > TBR) nv = TBR;
      }
      tcum += nt; off += n;
    }
    s_meta[0] = e; s_meta[1] = row0; s_meta[2] = nv;
  }
  __syncthreads();
  const int e      = s_meta[0];
  const int row0   = s_meta[1];
  const int nvalid = s_meta[2];
  if (e < 0) return;

  if (t < TBR){
    int li = (t < nvalid) ? (row0 + t) : row0;
    ridx[t] = g_sorted[li];
  }
  float* b1s = (float*)(smc + PARB1);
  float* gms = (float*)(smc + PARGM);
  float* bts = (float*)(smc + PARBT);
  float* b2s = (float*)(smc + PARB2);
  if (t < HDIM){
    b1s[t] = b1[e*HDIM + t];
    gms[t] = gamma[e*HDIM + t];
    bts[t] = beta[e*HDIM + t];
  }
  if (t < 128)
    b2s[t] = (t < CDIM) ? b2[e*CDIM + t] : 0.f;
  __syncthreads();

  const uint32_t smb = smem_u32(smc);
  const float* W1e = W1 + (size_t)e*FDIM*HDIM;
  const float* W2e = W2 + (size_t)e*HDIM*CDIM;
  const float* xrow = x + (size_t)ridx[t>>3]*FDIM + (t&7)*4;

  const int bn0 = w*8 + (lane&7);   // base n within 64-block
  const int kp0 = lane >> 3;

  // ---- stage chunk 0 (all 16 B sub-stages direct) ----
  {
    float4 v = *(const float4*)xrow;
    uint32_t h0,l0,h1,l1;
    split2(v.x,v.y,h0,l0); split2(v.z,v.w,h1,l1);
    char* Ad = smc + A1_OFF;
    *(uint2*)(Ad + (t>>3)*LDW + (t&7)*8)        = make_uint2(h0,h1);
    *(uint2*)(Ad + A1HL + (t>>3)*LDW + (t&7)*8) = make_uint2(l0,l1);
    char* Bd = smc + B1_OFF;
    #pragma unroll
    for (int ps=0;ps<2;ps++)
      #pragma unroll
      for (int p=0;p<2;p++){
        int n = ps*64 + p*128 + bn0;
        #pragma unroll
        for (int i=0;i<4;i++){
          int kp = i*4 + kp0;
          float v0 = W1e[(size_t)(2*kp)*HDIM + n];
          float v1 = W1e[(size_t)(2*kp+1)*HDIM + n];
          uint32_t hi, lo; split2(v0,v1,hi,lo);
          *(uint32_t*)(Bd + n*LDW + kp*4)        = hi;
          *(uint32_t*)(Bd + B1HL + n*LDW + kp*4) = lo;
        }
      }
  }
  __syncthreads();

  float acc1[2][4][4];
  #pragma unroll
  for (int mt=0;mt<2;mt++)
    #pragma unroll
    for (int nt=0;nt<4;nt++)
      #pragma unroll
      for (int q=0;q<4;q++) acc1[mt][nt][q] = 0.f;

  int buf = 0;
  #pragma unroll 1
  for (int kt=0; kt<NC1; ++kt){
    float4 pa; float2 pb[8];
    const bool more = (kt+1 < NC1);
    if (more){
      pa = *(const float4*)(xrow + (kt+1)*32);
      const float* Wb = W1e + (size_t)(kt+1)*32*HDIM;
      #pragma unroll
      for (int p=0;p<2;p++){
        int n = p*128 + bn0;        // pass 0: n in {0..63, 128..191}
        #pragma unroll
        for (int i=0;i<4;i++){
          int kp = i*4 + kp0;
          pb[p*4+i].x = Wb[(size_t)(2*kp)*HDIM + n];
          pb[p*4+i].y = Wb[(size_t)(2*kp+1)*HDIM + n];
        }
      }
    }
    // ---- compute on buf (rows 0..31, cols 32w..32w+31) ----
    {
      uint32_t ah[2][2][4], al[2][2][4];
      const uint32_t Ab = smb + A1_OFF + buf*A1BUF;
      #pragma unroll
      for (int mt=0;mt<2;mt++)
        #pragma unroll
        for (int kg=0;kg<2;kg++){
          uint32_t ad = Ab + (mt*16 + (lane&15))*LDW + kg*32 + (lane>>4)*16;
          ldsm4(ah[mt][kg], ad);
          ldsm4(al[mt][kg], ad + A1HL);
        }
      const uint32_t Bb = smb + B1_OFF + buf*B1BUF;
      #pragma unroll
      for (int nt=0;nt<4;nt++){
        uint32_t ba = Bb + (w*32 + nt*8 + (lane&7))*LDW + (lane>>3)*16;
        uint32_t bh[4], bl[4];
        ldsm4(bh, ba);
        ldsm4(bl, ba + B1HL);
        #pragma unroll
        for (int mt=0;mt<2;mt++)
          #pragma unroll
          for (int kg=0;kg<2;kg++){
            mma_bf16(acc1[mt][nt], ah[mt][kg], bh[2*kg], bh[2*kg+1]);
            mma_bf16(acc1[mt][nt], ah[mt][kg], bl[2*kg], bl[2*kg+1]);
            mma_bf16(acc1[mt][nt], al[mt][kg], bh[2*kg], bh[2*kg+1]);
          }
      }
    }
    // ---- store next chunk: prefetched pass 0, direct pass 1 ----
    if (more){
      int nb = buf ^ 1;
      uint32_t h0,l0,h1,l1;
      split2(pa.x,pa.y,h0,l0); split2(pa.z,pa.w,h1,l1);
      char* Ad = smc + A1_OFF + nb*A1BUF;
      *(uint2*)(Ad + (t>>3)*LDW + (t&7)*8)        = make_uint2(h0,h1);
      *(uint2*)(Ad + A1HL + (t>>3)*LDW + (t&7)*8) = make_uint2(l0,l1);
      char* Bd = smc + B1_OFF + nb*B1BUF;
      #pragma unroll
      for (int p=0;p<2;p++){
        int n = p*128 + bn0;
        #pragma unroll
        for (int i=0;i<4;i++){
          int kp = i*4 + kp0;
          uint32_t hi, lo; split2(pb[p*4+i].x, pb[p*4+i].y, hi, lo);
          *(uint32_t*)(Bd + n*LDW + kp*4)        = hi;
          *(uint32_t*)(Bd + B1HL + n*LDW + kp*4) = lo;
        }
      }
      {
        const float* Wb = W1e + (size_t)(kt+1)*32*HDIM;
        #pragma unroll
        for (int p=0;p<2;p++){
          int n = 64 + p*128 + bn0;   // pass 1
          #pragma unroll
          for (int i=0;i<4;i++){
            int kp = i*4 + kp0;
            float v0 = Wb[(size_t)(2*kp)*HDIM + n];
            float v1 = Wb[(size_t)(2*kp+1)*HDIM + n];
            uint32_t hi, lo; split2(v0,v1,hi,lo);
            *(uint32_t*)(Bd + n*LDW + kp*4)        = hi;
            *(uint32_t*)(Bd + B1HL + n*LDW + kp*4) = lo;
          }
        }
      }
      __syncthreads();
      buf = nb;
    }
  }

  // ---- + b1, LN stats (rows 0..31, 8 col-groups) ----
  float* psum = (float*)(smc + PSUM_OFF);
  float* psq  = (float*)(smc + PSQ_OFF);
  #pragma unroll
  for (int mt=0;mt<2;mt++)
    #pragma unroll
    for (int nt=0;nt<4;nt++)
      #pragma unroll
      for (int q=0;q<4;q++){
        int c = w*32 + nt*8 + 2*(lane&3) + (q&1);
        acc1[mt][nt][q] += b1s[c];
      }
  #pragma unroll
  for (int mt=0;mt<2;mt++)
    #pragma unroll
    for (int qh=0;qh<2;qh++){
      float s = 0.f, s2 = 0.f;
      #pragma unroll
      for (int nt=0;nt<4;nt++)
        #pragma unroll
        for (int ql=0;ql<2;ql++){
          float v = acc1[mt][nt][2*qh+ql];
          s += v; s2 += v*v;
        }
      s  += __shfl_xor_sync(0xffffffffu, s, 1);  s  += __shfl_xor_sync(0xffffffffu, s, 2);
      s2 += __shfl_xor_sync(0xffffffffu, s2, 1); s2 += __shfl_xor_sync(0xffffffffu, s2, 2);
      if ((lane & 3) == 0){
        int r = mt*16 + qh*8 + (lane>>2);
        psum[r*8 + w] = s;
        psq [r*8 + w] = s2;
      }
    }
  __syncthreads();
  if (t < TBR){
    float S = 0.f, S2 = 0.f;
    #pragma unroll
    for (int j=0;j<8;j++){ S += psum[t*8+j]; S2 += psq[t*8+j]; }
    float mu   = S * (1.0f/HDIM);
    float var  = S2 * (1.0f/HDIM) - mu*mu;
    float rstd = rsqrtf(var + 1e-5f);
    ((float2*)(smc + MURS_OFF))[t] = make_float2(mu, rstd);
  }
  __syncthreads();

  // ---- normalize + GELU -> A2 (bf16 hi/lo, [32][264]) ----
  {
    const float2* murs = (const float2*)(smc + MURS_OFF);
    #pragma unroll
    for (int mt=0;mt<2;mt++)
      #pragma unroll
      for (int qh=0;qh<2;qh++){
        int r = mt*16 + qh*8 + (lane>>2);
        float2 ms = murs[r];
        #pragma unroll
        for (int nt=0;nt<4;nt++){
          int c0 = w*32 + nt*8 + 2*(lane&3);
          float g0 = gelu((acc1[mt][nt][2*qh+0]-ms.x)*ms.y*gms[c0]   + bts[c0]);
          float g1 = gelu((acc1[mt][nt][2*qh+1]-ms.x)*ms.y*gms[c0+1] + bts[c0+1]);
          uint32_t hi, lo; split2(g0, g1, hi, lo);
          *(uint32_t*)(smc + A2_OFF + r*LDA2 + c0*2)        = hi;
          *(uint32_t*)(smc + A2_OFF + A2HL + r*LDA2 + c0*2) = lo;
        }
      }
  }
  __syncthreads();

  // ---- stage B2 chunk 0 ----
  {
    char* Bd = smc + B2_OFF;
    #pragma unroll
    for (int p=0;p<2;p++){
      int n = p*64 + bn0;             // 0..127
      #pragma unroll
      for (int i=0;i<4;i++){
        int kp = i*4 + kp0;
        float v0 = 0.f, v1 = 0.f;
        if (n < CDIM){
          v0 = W2e[(size_t)(2*kp)*CDIM + n];
          v1 = W2e[(size_t)(2*kp+1)*CDIM + n];
        }
        uint32_t hi, lo; split2(v0,v1,hi,lo);
        *(uint32_t*)(Bd + n*LDW + kp*4)        = hi;
        *(uint32_t*)(Bd + B2HL + n*LDW + kp*4) = lo;
      }
    }
  }
  __syncthreads();

  // ---- GEMM2: rows 0..31, warp cols 16w (warp tile 32x16) ----
  float acc2[2][2][4];
  #pragma unroll
  for (int mt=0;mt<2;mt++)
    #pragma unroll
    for (int nt=0;nt<2;nt++)
      #pragma unroll
      for (int q=0;q<4;q++) acc2[mt][nt][q] = 0.f;

  int b2buf = 0;
  #pragma unroll 1
  for (int kt2=0; kt2<NC2; ++kt2){
    float2 pb2[8];
    const bool more2 = (kt2+1 < NC2);
    if (more2){
      const float* Wb = W2e + (size_t)(kt2+1)*32*CDIM;
      #pragma unroll
      for (int p=0;p<2;p++){
        int n = p*64 + bn0;
        #pragma unroll
        for (int i=0;i<4;i++){
          int kp = i*4 + kp0;
          if (n < CDIM){
            pb2[p*4+i].x = Wb[(size_t)(2*kp)*CDIM + n];
            pb2[p*4+i].y = Wb[(size_t)(2*kp+1)*CDIM + n];
          } else { pb2[p*4+i].x = 0.f; pb2[p*4+i].y = 0.f; }
        }
      }
    }
    {
      uint32_t ah[2][2][4], al[2][2][4];
      #pragma unroll
      for (int mt=0;mt<2;mt++)
        #pragma unroll
        for (int kg=0;kg<2;kg++){
          uint32_t ad = smb + A2_OFF + (mt*16 + (lane&15))*LDA2
                      + kt2*64 + kg*32 + (lane>>4)*16;
          ldsm4(ah[mt][kg], ad);
          ldsm4(al[mt][kg], ad + A2HL);
        }
      const uint32_t Bb = smb + B2_OFF + b2buf*B2BUF;
      #pragma unroll
      for (int nt=0;nt<2;nt++){
        uint32_t ba = Bb + (w*16 + nt*8 + (lane&7))*LDW + (lane>>3)*16;
        uint32_t bh[4], bl[4];
        ldsm4(bh, ba);
        ldsm4(bl, ba + B2HL);
        #pragma unroll
        for (int mt=0;mt<2;mt++)
          #pragma unroll
          for (int kg=0;kg<2;kg++){
            mma_bf16(acc2[mt][nt], ah[mt][kg], bh[2*kg], bh[2*kg+1]);
            mma_bf16(acc2[mt][nt], ah[mt][kg], bl[2*kg], bl[2*kg+1]);
            mma_bf16(acc2[mt][nt], al[mt][kg], bh[2*kg], bh[2*kg+1]);
          }
      }
    }
    if (more2){
      int nb = b2buf ^ 1;
      char* Bd = smc + B2_OFF + nb*B2BUF;
      #pragma unroll
      for (int p=0;p<2;p++){
        int n = p*64 + bn0;
        #pragma unroll
        for (int i=0;i<4;i++){
          int kp = i*4 + kp0;
          uint32_t hi, lo; split2(pb2[p*4+i].x, pb2[p*4+i].y, hi, lo);
          *(uint32_t*)(Bd + n*LDW + kp*4)        = hi;
          *(uint32_t*)(Bd + B2HL + n*LDW + kp*4) = lo;
        }
      }
      __syncthreads();
      b2buf = nb;
    }
  }

  // ---- epilogue: + b2, scatter ----
  #pragma unroll
  for (int mt=0;mt<2;mt++)
    #pragma unroll
    for (int nt=0;nt<2;nt++)
      #pragma unroll
      for (int q=0;q<4;q++){
        int r = mt*16 + (lane>>2) + 8*(q>>1);
        int c = w*16 + nt*8 + 2*(lane&3) + (q&1);
        if (r < nvalid && c < CDIM)
          out[(size_t)ridx[r]*CDIM + c] = acc2[mt][nt][q] + b2s[c];
      }
}

// ---------------------------------------------------------------------------
extern "C" void kernel_launch(void* const* d_in, const int* in_sizes, int n_in,
                              void* d_out, int out_size){
  (void)in_sizes; (void)n_in; (void)out_size;
  const float* x      = (const float*)d_in[0];
  const float* protos = (const float*)d_in[1];
  const float* gnew   = (const float*)d_in[2];
  const float* gmem   = (const float*)d_in[3];
  const int*   cc     = (const int*)  d_in[4];
  const float* W1     = (const float*)d_in[5];
  const float* b1     = (const float*)d_in[6];
  const float* gamma  = (const float*)d_in[7];
  const float* beta   = (const float*)d_in[8];
  const float* W2     = (const float*)d_in[9];
  const float* b2     = (const float*)d_in[10];
  float* out = (float*)d_out;

  prep_kernel<<<EDIM, 128>>>(protos, gnew, gmem, cc);
  route_kernel<<<BDIM/32, 256>>>(x, protos);
  scatter_kernel<<<BDIM/256, 256>>>();

  cudaFuncSetAttribute(mlp_kernel, cudaFuncAttributeMaxDynamicSharedMemorySize, DYNB);
  mlp_kernel<<<MAXT, NTHR, DYNB>>>(x, W1, b1, gamma, beta, W2, b2, out);
}

// round 16
// speedup vs baseline: 1.2508x; 1.2508x over previous
#include <cuda_runtime.h>
#include <cuda_bf16.h>
#include <math.h>
#include <stdint.h>

#define BDIM 8192
#define FDIM 1024
#define EDIM 30
#define HDIM 256
#define CDIM 100
#define GDIM 4096
#define EPSV 1e-8f

#define TBR  64
#define NTHR 512
#define MAXT 160
#define NC1  32      /* 1024/32 k-chunks GEMM1 */
#define NC2  8       /* 256/32  k-chunks GEMM2 */

/* ---- dynamic smem layout (bytes) ---- */
#define LDW    80        /* A1 row stride: 40 bf16 */
#define A1HL   5120
#define A1BUF  10240
#define A1_OFF 0         /* 2 buffers -> 20480 */
#define B1_OFF 20480     /* B1: [k=32][n=256] natural */
#define LDB1   528
#define B1HL   16896
#define B1BUF  33792     /* 2 buffers -> ends 88064 */
#define PARB1  88064
#define PARGM  89088
#define PARBT  90112
#define PARB2  91136
#define PSUM_OFF 92160
#define PSQ_OFF  94208
#define MURS_OFF 96256
#define A2_OFF 97280     /* [64][264 bf16] */
#define LDA2   528
#define A2HL   33792     /* hi+lo -> ends 164864 */
#define B2_OFF 164864    /* B2: [k=32][n=128] natural */
#define LDB2   272
#define B2HL   8704
#define B2BUF  17408     /* 2 buffers -> ends 199680 */
#define DYNB   199680

__device__ int   g_assign[BDIM];
__device__ int   g_counts[EDIM];
__device__ int   g_cursor[EDIM];
__device__ float g_escale[EDIM];
__device__ int   g_sorted[BDIM];

__device__ __forceinline__ float warp_sum(float v){
  #pragma unroll
  for (int o=16;o>0;o>>=1) v += __shfl_xor_sync(0xffffffffu, v, o);
  return v;
}

__device__ __forceinline__ uint32_t smem_u32(const void* p){
  uint32_t a;
  asm("{ .reg .u64 t; cvta.to.shared.u64 t, %1; cvt.u32.u64 %0, t; }" : "=r"(a) : "l"(p));
  return a;
}

__device__ __forceinline__ void split2(float v0, float v1, uint32_t& hi, uint32_t& lo){
  __nv_bfloat16 h0 = __float2bfloat16(v0), h1 = __float2bfloat16(v1);
  float r0 = v0 - __bfloat162float(h0), r1 = v1 - __bfloat162float(h1);
  __nv_bfloat162 hp; hp.x = h0; hp.y = h1;
  __nv_bfloat162 lp = __floats2bfloat162_rn(r0, r1);
  hi = *(uint32_t*)&hp; lo = *(uint32_t*)&lp;
}

__device__ __forceinline__ void ldsm4(uint32_t* r, uint32_t a){
  asm volatile("ldmatrix.sync.aligned.m8n8.x4.shared.b16 {%0,%1,%2,%3}, [%4];"
    : "=r"(r[0]),"=r"(r[1]),"=r"(r[2]),"=r"(r[3]) : "r"(a));
}
__device__ __forceinline__ void ldsm4t(uint32_t* r, uint32_t a){
  asm volatile("ldmatrix.sync.aligned.m8n8.x4.trans.shared.b16 {%0,%1,%2,%3}, [%4];"
    : "=r"(r[0]),"=r"(r[1]),"=r"(r[2]),"=r"(r[3]) : "r"(a));
}
__device__ __forceinline__ void mma_bf16(float* d, const uint32_t* a, uint32_t b0, uint32_t b1){
  asm volatile("mma.sync.aligned.m16n8k16.row.col.f32.bf16.bf16.f32 "
    "{%0,%1,%2,%3}, {%4,%5,%6,%7}, {%8,%9}, {%0,%1,%2,%3};"
    : "+f"(d[0]),"+f"(d[1]),"+f"(d[2]),"+f"(d[3])
    : "r"(a[0]),"r"(a[1]),"r"(a[2]),"r"(a[3]), "r"(b0),"r"(b1));
}
__device__ __forceinline__ float gelu(float v){
  return 0.5f*v*(1.0f + erff(v*0.70710678118654752f));
}

// ---------------------------------------------------------------------------
__global__ void prep_kernel(const float* __restrict__ protos,
                            const float* __restrict__ gnew,
                            const float* __restrict__ gmem,
                            const int*   __restrict__ class_counts){
  int e = blockIdx.x;
  int t = threadIdx.x, lane = t & 31, w = t >> 5;
  __shared__ float red[4][4];
  if (t == 0){ g_counts[e] = 0; g_cursor[e] = 0; }
  float d = 0.f, m2 = 0.f, n2 = 0.f;
  for (int i = t; i < GDIM; i += 128){
    float a = gmem[(size_t)e*GDIM + i];
    float b = gnew[i];
    d += a*b; m2 += a*a; n2 += b*b;
  }
  float p2 = 0.f;
  for (int f = t; f < FDIM; f += 128){
    float p = protos[(size_t)e*FDIM + f];
    p2 += p*p;
  }
  d = warp_sum(d); m2 = warp_sum(m2); n2 = warp_sum(n2); p2 = warp_sum(p2);
  if (lane == 0){ red[w][0]=d; red[w][1]=m2; red[w][2]=n2; red[w][3]=p2; }
  __syncthreads();
  if (t == 0){
    float D=0.f,M=0.f,N=0.f,P=0.f;
    #pragma unroll
    for (int i=0;i<4;i++){ D+=red[i][0]; M+=red[i][1]; N+=red[i][2]; P+=red[i][3]; }
    float align = 0.5f*(1.0f + D/((sqrtf(M)+EPSV)*(sqrtf(N)+EPSV)));
    float over  = fmaxf((float)class_counts[e]/5.0f - 1.0f, 0.0f);
    float cap   = expf(-1.5f*over);
    g_escale[e] = align*cap/(sqrtf(P)+EPSV);
  }
}

__global__ __launch_bounds__(256, 2) void route_kernel(
    const float* __restrict__ x, const float* __restrict__ protos){
  __shared__ float xt[64][33];
  __shared__ float pr[30][64];
  __shared__ float sc[32][32];
  const int t = threadIdx.x;
  const int sample = t & 31;
  const int egr    = t >> 5;
  const int s0 = blockIdx.x * 32;

  float acc[4] = {0.f,0.f,0.f,0.f};
  for (int kt = 0; kt < 16; ++kt){
    __syncthreads();
    {
      int kk = t & 63, rr = t >> 6;
      #pragma unroll
      for (int i=0;i<8;i++){
        int r = rr + 4*i;
        xt[kk][r] = x[(size_t)(s0 + r)*FDIM + kt*64 + kk];
      }
    }
    #pragma unroll
    for (int i=0;i<8;i++){
      int idx = t + 256*i;
      if (idx < 1920)
        pr[idx >> 6][idx & 63] = protos[(size_t)(idx >> 6)*FDIM + kt*64 + (idx & 63)];
    }
    __syncthreads();
    #pragma unroll
    for (int k4 = 0; k4 < 16; ++k4){
      float x0 = xt[4*k4+0][sample], x1 = xt[4*k4+1][sample];
      float x2 = xt[4*k4+2][sample], x3 = xt[4*k4+3][sample];
      #pragma unroll
      for (int e4 = 0; e4 < 4; ++e4){
        int e = egr*4 + e4;
        if (e < EDIM){
          float4 p = *(const float4*)&pr[e][4*k4];
          acc[e4] += x0*p.x + x1*p.y + x2*p.z + x3*p.w;
        }
      }
    }
  }
  #pragma unroll
  for (int e4 = 0; e4 < 4; ++e4){
    int e = egr*4 + e4;
    if (e < 32) sc[sample][e & 31] = (e < EDIM) ? acc[e4] : 0.f;
  }
  __syncthreads();
  if (t < 32){
    float best = -3.4e38f; int bi = 0;
    #pragma unroll 1
    for (int e = 0; e < EDIM; ++e){
      float s = sc[t][e] * g_escale[e];
      if (s > best){ best = s; bi = e; }
    }
    g_assign[s0 + t] = bi;
    atomicAdd(&g_counts[bi], 1);
  }
}

__global__ void scatter_kernel(){
  __shared__ int base[EDIM];
  if (threadIdx.x == 0){
    int off = 0;
    #pragma unroll
    for (int e=0;e<EDIM;e++){ base[e] = off; off += g_counts[e]; }
  }
  __syncthreads();
  int b = blockIdx.x*blockDim.x + threadIdx.x;
  if (b < BDIM){
    int e = g_assign[b];
    int pos = base[e] + atomicAdd(&g_cursor[e], 1);
    g_sorted[pos] = b;
  }
}

// ---------------------------------------------------------------------------
// MLP: bf16 split mma.sync; W staged in NATURAL [k][n] layout with coalesced
// float4 LDG + vector STS, consumed via ldmatrix.x4.trans.
// ---------------------------------------------------------------------------
__global__ __launch_bounds__(NTHR, 1)
void mlp_kernel(const float* __restrict__ x,  const float* __restrict__ W1,
                const float* __restrict__ b1, const float* __restrict__ gamma,
                const float* __restrict__ beta, const float* __restrict__ W2,
                const float* __restrict__ b2, float* __restrict__ out)
{
  extern __shared__ __align__(128) char smc[];
  __shared__ int ridx[TBR];
  __shared__ int s_meta[3];

  const int t    = threadIdx.x;
  const int lane = t & 31;
  const int w    = t >> 5;        // 0..15
  const int wm   = w >> 3;        // GEMM1 rows 32*wm
  const int wn   = w & 7;         // GEMM1 cols 32*wn

  if (t == 0){
    int off = 0, tcum = 0, e = -1, row0 = 0, nv = 0;
    #pragma unroll 1
    for (int ee=0; ee<EDIM; ee++){
      int n  = g_counts[ee];
      int nt = (n + TBR - 1) / TBR;
      if (e < 0 && (int)blockIdx.x < tcum + nt){
        int li = (int)blockIdx.x - tcum;
        e = ee; row0 = off + li*TBR;
        nv = n - li*TBR; if (nv > TBR) nv = TBR;
      }
      tcum += nt; off += n;
    }
    s_meta[0] = e; s_meta[1] = row0; s_meta[2] = nv;
  }
  __syncthreads();
  const int e      = s_meta[0];
  const int row0   = s_meta[1];
  const int nvalid = s_meta[2];
  if (e < 0) return;

  if (t < TBR){
    int li = (t < nvalid) ? (row0 + t) : row0;
    ridx[t] = g_sorted[li];
  }
  float* b1s = (float*)(smc + PARB1);
  float* gms = (float*)(smc + PARGM);
  float* bts = (float*)(smc + PARBT);
  float* b2s = (float*)(smc + PARB2);
  if (t < HDIM){
    b1s[t] = b1[e*HDIM + t];
    gms[t] = gamma[e*HDIM + t];
    bts[t] = beta[e*HDIM + t];
  }
  if (t >= HDIM && t < HDIM+128){
    int c = t - HDIM;
    b2s[c] = (c < CDIM) ? b2[e*CDIM + c] : 0.f;
  }
  __syncthreads();

  const uint32_t smb = smem_u32(smc);
  const float* W1e = W1 + (size_t)e*FDIM*HDIM;
  const float* W2e = W2 + (size_t)e*HDIM*CDIM;
  const float* xrow = x + (size_t)ridx[t>>3]*FDIM + (t&7)*4;

  /* B1 staging indices: idx = t + 512*i -> k row, n-float4 col */
  const int b1k[4]  = { t>>6, (t+512)>>6, (t+1024)>>6, (t+1536)>>6 };
  const int b1c4    = t & 63;

  // ---- stage chunk 0 ----
  {
    float4 v = *(const float4*)xrow;
    uint32_t h0,l0,h1,l1;
    split2(v.x,v.y,h0,l0); split2(v.z,v.w,h1,l1);
    char* Ad = smc + A1_OFF;
    *(uint2*)(Ad + (t>>3)*LDW + (t&7)*8)        = make_uint2(h0,h1);
    *(uint2*)(Ad + A1HL + (t>>3)*LDW + (t&7)*8) = make_uint2(l0,l1);
    char* Bd = smc + B1_OFF;
    #pragma unroll
    for (int i=0;i<4;i++){
      int k = b1k[i];
      float4 wv = *(const float4*)(W1e + (size_t)k*HDIM + b1c4*4);
      uint32_t hA,lA,hB,lB;
      split2(wv.x,wv.y,hA,lA); split2(wv.z,wv.w,hB,lB);
      *(uint2*)(Bd + k*LDB1 + b1c4*8)        = make_uint2(hA,hB);
      *(uint2*)(Bd + B1HL + k*LDB1 + b1c4*8) = make_uint2(lA,lB);
    }
  }
  __syncthreads();

  float acc1[2][4][4];
  #pragma unroll
  for (int mt=0;mt<2;mt++)
    #pragma unroll
    for (int nt=0;nt<4;nt++)
      #pragma unroll
      for (int q=0;q<4;q++) acc1[mt][nt][q] = 0.f;

  int buf = 0;
  #pragma unroll 1
  for (int kt=0; kt<NC1; ++kt){
    float4 pa; float4 pb[4];
    const bool more = (kt+1 < NC1);
    if (more){
      pa = *(const float4*)(xrow + (kt+1)*32);
      const float* Wb = W1e + (size_t)(kt+1)*32*HDIM;
      #pragma unroll
      for (int i=0;i<4;i++)
        pb[i] = *(const float4*)(Wb + (size_t)b1k[i]*HDIM + b1c4*4);
    }
    // ---- compute on buf ----
    {
      uint32_t ah[2][2][4], al[2][2][4];
      const uint32_t Ab = smb + A1_OFF + buf*A1BUF;
      #pragma unroll
      for (int mt=0;mt<2;mt++)
        #pragma unroll
        for (int kg=0;kg<2;kg++){
          uint32_t ad = Ab + (wm*32 + mt*16 + (lane&15))*LDW + kg*32 + (lane>>4)*16;
          ldsm4(ah[mt][kg], ad);
          ldsm4(al[mt][kg], ad + A1HL);
        }
      const uint32_t Bb = smb + B1_OFF + buf*B1BUF;
      #pragma unroll
      for (int np=0; np<2; ++np){
        uint32_t bh[2][4], bl[2][4];   // [kh][frag]
        #pragma unroll
        for (int kh=0; kh<2; ++kh){
          uint32_t ba = Bb + (uint32_t)(kh*16 + (lane&15))*LDB1
                      + (uint32_t)(wn*32 + np*16 + (lane>>4)*8)*2;
          ldsm4t(bh[kh], ba);
          ldsm4t(bl[kh], ba + B1HL);
        }
        #pragma unroll
        for (int sub=0; sub<2; ++sub){
          int nt = np*2 + sub;
          #pragma unroll
          for (int mt=0;mt<2;mt++)
            #pragma unroll
            for (int kg=0;kg<2;kg++){
              mma_bf16(acc1[mt][nt], ah[mt][kg], bh[kg][sub*2], bh[kg][sub*2+1]);
              mma_bf16(acc1[mt][nt], ah[mt][kg], bl[kg][sub*2], bl[kg][sub*2+1]);
              mma_bf16(acc1[mt][nt], al[mt][kg], bh[kg][sub*2], bh[kg][sub*2+1]);
            }
        }
      }
    }
    // ---- convert + store next chunk ----
    if (more){
      int nb = buf ^ 1;
      uint32_t h0,l0,h1,l1;
      split2(pa.x,pa.y,h0,l0); split2(pa.z,pa.w,h1,l1);
      char* Ad = smc + A1_OFF + nb*A1BUF;
      *(uint2*)(Ad + (t>>3)*LDW + (t&7)*8)        = make_uint2(h0,h1);
      *(uint2*)(Ad + A1HL + (t>>3)*LDW + (t&7)*8) = make_uint2(l0,l1);
      char* Bd = smc + B1_OFF + nb*B1BUF;
      #pragma unroll
      for (int i=0;i<4;i++){
        int k = b1k[i];
        uint32_t hA,lA,hB,lB;
        split2(pb[i].x,pb[i].y,hA,lA); split2(pb[i].z,pb[i].w,hB,lB);
        *(uint2*)(Bd + k*LDB1 + b1c4*8)        = make_uint2(hA,hB);
        *(uint2*)(Bd + B1HL + k*LDB1 + b1c4*8) = make_uint2(lA,lB);
      }
      __syncthreads();
      buf = nb;
    }
  }

  // ---- + b1, LN stats ----
  float* psum = (float*)(smc + PSUM_OFF);
  float* psq  = (float*)(smc + PSQ_OFF);
  #pragma unroll
  for (int mt=0;mt<2;mt++)
    #pragma unroll
    for (int nt=0;nt<4;nt++)
      #pragma unroll
      for (int q=0;q<4;q++){
        int c = wn*32 + nt*8 + 2*(lane&3) + (q&1);
        acc1[mt][nt][q] += b1s[c];
      }
  #pragma unroll
  for (int mt=0;mt<2;mt++)
    #pragma unroll
    for (int qh=0;qh<2;qh++){
      float s = 0.f, s2 = 0.f;
      #pragma unroll
      for (int nt=0;nt<4;nt++)
        #pragma unroll
        for (int ql=0;ql<2;ql++){
          float v = acc1[mt][nt][2*qh+ql];
          s += v; s2 += v*v;
        }
      s  += __shfl_xor_sync(0xffffffffu, s, 1);  s  += __shfl_xor_sync(0xffffffffu, s, 2);
      s2 += __shfl_xor_sync(0xffffffffu, s2, 1); s2 += __shfl_xor_sync(0xffffffffu, s2, 2);
      if ((lane & 3) == 0){
        int r = wm*32 + mt*16 + qh*8 + (lane>>2);
        psum[r*8 + wn] = s;
        psq [r*8 + wn] = s2;
      }
    }
  __syncthreads();
  if (t < TBR){
    float S = 0.f, S2 = 0.f;
    #pragma unroll
    for (int j=0;j<8;j++){ S += psum[t*8+j]; S2 += psq[t*8+j]; }
    float mu   = S * (1.0f/HDIM);
    float var  = S2 * (1.0f/HDIM) - mu*mu;
    float rstd = rsqrtf(var + 1e-5f);
    ((float2*)(smc + MURS_OFF))[t] = make_float2(mu, rstd);
  }
  __syncthreads();

  // ---- normalize + GELU -> A2 (bf16 hi/lo, [64][264]) ----
  {
    const float2* murs = (const float2*)(smc + MURS_OFF);
    #pragma unroll
    for (int mt=0;mt<2;mt++)
      #pragma unroll
      for (int qh=0;qh<2;qh++){
        int r = wm*32 + mt*16 + qh*8 + (lane>>2);
        float2 ms = murs[r];
        #pragma unroll
        for (int nt=0;nt<4;nt++){
          int c0 = wn*32 + nt*8 + 2*(lane&3);
          float g0 = gelu((acc1[mt][nt][2*qh+0]-ms.x)*ms.y*gms[c0]   + bts[c0]);
          float g1 = gelu((acc1[mt][nt][2*qh+1]-ms.x)*ms.y*gms[c0+1] + bts[c0+1]);
          uint32_t hi, lo; split2(g0, g1, hi, lo);
          *(uint32_t*)(smc + A2_OFF + r*LDA2 + c0*2)        = hi;
          *(uint32_t*)(smc + A2_OFF + A2HL + r*LDA2 + c0*2) = lo;
        }
      }
  }

  /* B2 staging indices: idx = t + 512*i -> k row (32 f4/row), c4 col */
  const int b2k[2] = { t>>5, (t+512)>>5 };
  const int b2c4   = t & 31;

  // ---- stage B2 chunk 0 ----
  {
    char* Bd = smc + B2_OFF;
    #pragma unroll
    for (int i=0;i<2;i++){
      int k = b2k[i];
      float4 wv = make_float4(0.f,0.f,0.f,0.f);
      if (b2c4 < 25)
        wv = *(const float4*)(W2e + (size_t)k*CDIM + b2c4*4);
      uint32_t hA,lA,hB,lB;
      split2(wv.x,wv.y,hA,lA); split2(wv.z,wv.w,hB,lB);
      *(uint2*)(Bd + k*LDB2 + b2c4*8)        = make_uint2(hA,hB);
      *(uint2*)(Bd + B2HL + k*LDB2 + b2c4*8) = make_uint2(lA,lB);
    }
  }
  __syncthreads();

  // ---- GEMM2: warp grid M2 x N8, warp tile 32x16 ----
  float acc2[2][2][4];
  #pragma unroll
  for (int mt=0;mt<2;mt++)
    #pragma unroll
    for (int nt=0;nt<2;nt++)
      #pragma unroll
      for (int q=0;q<4;q++) acc2[mt][nt][q] = 0.f;

  const int wm2 = w & 1;          // rows 32*wm2
  const int wn2 = w >> 1;         // cols 16*wn2
  int b2buf = 0;
  #pragma unroll 1
  for (int kt2=0; kt2<NC2; ++kt2){
    float4 pb2[2];
    const bool more2 = (kt2+1 < NC2);
    if (more2){
      const float* Wb = W2e + (size_t)(kt2+1)*32*CDIM;
      #pragma unroll
      for (int i=0;i<2;i++){
        pb2[i] = make_float4(0.f,0.f,0.f,0.f);
        if (b2c4 < 25)
          pb2[i] = *(const float4*)(Wb + (size_t)b2k[i]*CDIM + b2c4*4);
      }
    }
    {
      uint32_t ah[2][2][4], al[2][2][4];
      #pragma unroll
      for (int mt=0;mt<2;mt++)
        #pragma unroll
        for (int kg=0;kg<2;kg++){
          uint32_t ad = smb + A2_OFF + (wm2*32 + mt*16 + (lane&15))*LDA2
                      + kt2*64 + kg*32 + (lane>>4)*16;
          ldsm4(ah[mt][kg], ad);
          ldsm4(al[mt][kg], ad + A2HL);
        }
      const uint32_t Bb = smb + B2_OFF + b2buf*B2BUF;
      uint32_t bh[2][4], bl[2][4];
      #pragma unroll
      for (int kh=0; kh<2; ++kh){
        uint32_t ba = Bb + (uint32_t)(kh*16 + (lane&15))*LDB2
                    + (uint32_t)(wn2*16 + (lane>>4)*8)*2;
        ldsm4t(bh[kh], ba);
        ldsm4t(bl[kh], ba + B2HL);
      }
      #pragma unroll
      for (int nt=0;nt<2;nt++)
        #pragma unroll
        for (int mt=0;mt<2;mt++)
          #pragma unroll
          for (int kg=0;kg<2;kg++){
            mma_bf16(acc2[mt][nt], ah[mt][kg], bh[kg][nt*2], bh[kg][nt*2+1]);
            mma_bf16(acc2[mt][nt], ah[mt][kg], bl[kg][nt*2], bl[kg][nt*2+1]);
            mma_bf16(acc2[mt][nt], al[mt][kg], bh[kg][nt*2], bh[kg][nt*2+1]);
          }
    }
    if (more2){
      int nb = b2buf ^ 1;
      char* Bd = smc + B2_OFF + nb*B2BUF;
      #pragma unroll
      for (int i=0;i<2;i++){
        int k = b2k[i];
        uint32_t hA,lA,hB,lB;
        split2(pb2[i].x,pb2[i].y,hA,lA); split2(pb2[i].z,pb2[i].w,hB,lB);
        *(uint2*)(Bd + k*LDB2 + b2c4*8)        = make_uint2(hA,hB);
        *(uint2*)(Bd + B2HL + k*LDB2 + b2c4*8) = make_uint2(lA,lB);
      }
      __syncthreads();
      b2buf = nb;
    }
  }

  // ---- epilogue: + b2, scatter ----
  #pragma unroll
  for (int mt=0;mt<2;mt++)
    #pragma unroll
    for (int nt=0;nt<2;nt++)
      #pragma unroll
      for (int q=0;q<4;q++){
        int r = wm2*32 + mt*16 + (lane>>2) + 8*(q>>1);
        int c = wn2*16 + nt*8 + 2*(lane&3) + (q&1);
        if (r < nvalid && c < CDIM)
          out[(size_t)ridx[r]*CDIM + c] = acc2[mt][nt][q] + b2s[c];
      }
}

// ---------------------------------------------------------------------------
extern "C" void kernel_launch(void* const* d_in, const int* in_sizes, int n_in,
                              void* d_out, int out_size){
  (void)in_sizes; (void)n_in; (void)out_size;
  const float* x      = (const float*)d_in[0];
  const float* protos = (const float*)d_in[1];
  const float* gnew   = (const float*)d_in[2];
  const float* gmem   = (const float*)d_in[3];
  const int*   cc     = (const int*)  d_in[4];
  const float* W1     = (const float*)d_in[5];
  const float* b1     = (const float*)d_in[6];
  const float* gamma  = (const float*)d_in[7];
  const float* beta   = (const float*)d_in[8];
  const float* W2     = (const float*)d_in[9];
  const float* b2     = (const float*)d_in[10];
  float* out = (float*)d_out;

  prep_kernel<<<EDIM, 128>>>(protos, gnew, gmem, cc);
  route_kernel<<<BDIM/32, 256>>>(x, protos);
  scatter_kernel<<<BDIM/256, 256>>>();

  cudaFuncSetAttribute(mlp_kernel, cudaFuncAttributeMaxDynamicSharedMemorySize, DYNB);
  mlp_kernel<<<MAXT, NTHR, DYNB>>>(x, W1, b1, gamma, beta, W2, b2, out);
}